// round 1
// baseline (speedup 1.0000x reference)
#include <cuda_runtime.h>
#include <math_constants.h>

#define HH 256
#define WW 256
#define NIMG 512          // B*C = 8*64
#define CCH 64
#define HWSZ 65536        // 256*256

// Scratch (static device globals — no runtime allocation)
__device__ float g_dst[NIMG * HWSZ];   // dilated Harris response
__device__ float g_max[NIMG];          // per-image max of dst

__device__ __forceinline__ void atomicMaxFloat(float* addr, float val) {
    if (val >= 0.f) atomicMax((int*)addr, __float_as_int(val));
    else            atomicMin((unsigned int*)addr, __float_as_uint(val));
}

__global__ void init_max_kernel() {
    int i = blockIdx.x * blockDim.x + threadIdx.x;
    if (i < NIMG) g_max[i] = -CUDART_INF_F;
}

// ---------------------------------------------------------------------------
// Pass A: Harris response R -> 3x3 dilation dst, per-image max.
// One warp per (image, 64-row segment). Each lane owns 8 columns (full 256-wide
// row per warp). All intermediates in registers; horizontal neighbor exchange
// via warp shuffles at lane boundaries only.
// ---------------------------------------------------------------------------

// load x row r (reflect-101 row index) into 8 regs per lane (two float4 LDGs)
#define LOAD_XROW(r, dst_)  do {                                              \
    int rr__ = (r);                                                           \
    rr__ = (rr__ < 0) ? -rr__ : ((rr__ >= HH) ? (2*HH - 2 - rr__) : rr__);    \
    const float4* p__ = reinterpret_cast<const float4*>(xim + rr__ * WW + cb);\
    float4 q0__ = p__[0], q1__ = p__[1];                                      \
    dst_[0]=q0__.x; dst_[1]=q0__.y; dst_[2]=q0__.z; dst_[3]=q0__.w;           \
    dst_[4]=q1__.x; dst_[5]=q1__.y; dst_[6]=q1__.z; dst_[7]=q1__.w;           \
} while(0)

// Compute gradient-product row (row): dxx, dxy, dyy. Advances x window.
// Column reflect for the Sobel is automatic: out-of-image x columns are never
// held (warp spans exactly cols 0..255) and the needed reflected value equals
// the in-image neighbor (u(-1)==u(1)), provided by the lane-0/31 selects.
#define COMPUTE_DD(row, AX, AXY, AY) do {                                     \
    float xc__[8]; LOAD_XROW((row)+1, xc__);                                  \
    float u__[8], v__[8];                                                     \
    _Pragma("unroll")                                                         \
    for (int i=0;i<8;i++){ u__[i] = xa[i] + 2.0f*xb[i] + xc__[i];             \
                           v__[i] = xc__[i] - xa[i]; }                        \
    float uL__ = __shfl_up_sync(0xffffffffu, u__[7], 1);                      \
    float uR__ = __shfl_down_sync(0xffffffffu, u__[0], 1);                    \
    float vL__ = __shfl_up_sync(0xffffffffu, v__[7], 1);                      \
    float vR__ = __shfl_down_sync(0xffffffffu, v__[0], 1);                    \
    if (lane == 0)  { uL__ = u__[1]; vL__ = v__[1]; }                         \
    if (lane == 31) { uR__ = u__[6]; vR__ = v__[6]; }                         \
    _Pragma("unroll")                                                         \
    for (int i=0;i<8;i++){                                                    \
        float um1__ = (i==0)? uL__ : u__[i-1];                                \
        float up1__ = (i==7)? uR__ : u__[i+1];                                \
        float vm1__ = (i==0)? vL__ : v__[i-1];                                \
        float vp1__ = (i==7)? vR__ : v__[i+1];                                \
        float dx__ = (up1__ - um1__) * SC;                                    \
        float dy__ = (vm1__ + 2.0f*v__[i] + vp1__) * SC;                      \
        AX[i] = dx__*dx__; AXY[i] = dx__*dy__; AY[i] = dy__*dy__;             \
    }                                                                         \
    _Pragma("unroll")                                                         \
    for (int i=0;i<8;i++){ xa[i] = xb[i]; xb[i] = xc__[i]; }                  \
} while(0)

__global__ void __launch_bounds__(32) harris_kernel(const float* __restrict__ x) {
    const int img  = blockIdx.x >> 2;
    const int seg  = blockIdx.x & 3;
    const int lane = threadIdx.x;
    const int cb   = lane * 8;
    const float* __restrict__ xim = x + (size_t)img * HWSZ;
    float* __restrict__ dim_ = g_dst + (size_t)img * HWSZ;

    const int r0  = seg * 64;
    const int r1  = r0 + 64;
    const int Rlo = (r0 == 0) ? 0 : (r0 - 1);
    const int Rhi = (r1 == HH) ? HH : (r1 + 1);

    const float SC = (1.0f / 12.0f);   // SOBEL_SCALE

    float xa[8], xb[8];
    float axp[8], axyp[8], ayp[8];   // dd row p-1
    float axc[8], axyc[8], ayc[8];   // dd row p
    float axn[8], axyn[8], ayn[8];   // dd row p+1
    float ma[8], mb[8];              // horizontal-max windows m(p-1), m(p-2)
    float lmax = -CUDART_INF_F;

#pragma unroll
    for (int i=0;i<8;i++){ axp[i]=axyp[i]=ayp[i]=0.f; ma[i]=mb[i]=0.f; }

    if (Rlo == 0) {
        LOAD_XROW(-1, xa);
        LOAD_XROW(0,  xb);
        COMPUTE_DD(0, axc, axyc, ayc);
        COMPUTE_DD(1, axn, axyn, ayn);
    } else {
        LOAD_XROW(Rlo - 2, xa);
        LOAD_XROW(Rlo - 1, xb);
        COMPUTE_DD(Rlo - 1, axp, axyp, ayp);
        COMPUTE_DD(Rlo,     axc, axyc, ayc);
        COMPUTE_DD(Rlo + 1, axn, axyn, ayn);
    }

    for (int p = Rlo; p < Rhi; ++p) {
        // vertical box sum with reflect-101 of the dd field at image borders
        float sxx[8], sxy[8], syy[8];
        if (p == 0) {
#pragma unroll
            for (int i=0;i<8;i++){ sxx[i]=axc[i]+2.0f*axn[i];
                                   sxy[i]=axyc[i]+2.0f*axyn[i];
                                   syy[i]=ayc[i]+2.0f*ayn[i]; }
        } else if (p == HH-1) {
#pragma unroll
            for (int i=0;i<8;i++){ sxx[i]=axc[i]+2.0f*axp[i];
                                   sxy[i]=axyc[i]+2.0f*axyp[i];
                                   syy[i]=ayc[i]+2.0f*ayp[i]; }
        } else {
#pragma unroll
            for (int i=0;i<8;i++){ sxx[i]=axp[i]+axc[i]+axn[i];
                                   sxy[i]=axyp[i]+axyc[i]+axyn[i];
                                   syy[i]=ayp[i]+ayc[i]+ayn[i]; }
        }
        // horizontal box sum (reflect-101 of dd field at cols 0 / W-1)
        float xxL = __shfl_up_sync(0xffffffffu, sxx[7],1);
        float xxR = __shfl_down_sync(0xffffffffu, sxx[0],1);
        float xyL = __shfl_up_sync(0xffffffffu, sxy[7],1);
        float xyR = __shfl_down_sync(0xffffffffu, sxy[0],1);
        float yyL = __shfl_up_sync(0xffffffffu, syy[7],1);
        float yyR = __shfl_down_sync(0xffffffffu, syy[0],1);
        if (lane==0){  xxL=sxx[1]; xyL=sxy[1]; yyL=syy[1]; }
        if (lane==31){ xxR=sxx[6]; xyR=sxy[6]; yyR=syy[6]; }
        float Rv[8];
#pragma unroll
        for (int i=0;i<8;i++){
            float ixx = ((i==0)?xxL:sxx[i-1]) + sxx[i] + ((i==7)?xxR:sxx[i+1]);
            float ixy = ((i==0)?xyL:sxy[i-1]) + sxy[i] + ((i==7)?xyR:sxy[i+1]);
            float iyy = ((i==0)?yyL:syy[i-1]) + syy[i] + ((i==7)?yyR:syy[i+1]);
            float det = ixx*iyy - ixy*ixy;
            float tr  = ixx + iyy;
            Rv[i] = det - 0.04f * tr * tr;   // HARRIS_K
        }
        // horizontal 3-max (dilation clips at image border: -inf outside)
        float RL = __shfl_up_sync(0xffffffffu, Rv[7],1);
        float RR = __shfl_down_sync(0xffffffffu, Rv[0],1);
        if (lane==0)  RL = -CUDART_INF_F;
        if (lane==31) RR = -CUDART_INF_F;
        float mc[8];
#pragma unroll
        for (int i=0;i<8;i++){
            float l = (i==0)?RL:Rv[i-1];
            float r = (i==7)?RR:Rv[i+1];
            mc[i] = fmaxf(fmaxf(l, Rv[i]), r);
        }
        // emit dst row q = p-1 (vertical 3-max, clipped at image borders)
        int q = p - 1;
        if (q >= r0) {
            float dv[8];
            if (q == 0) {
#pragma unroll
                for (int i=0;i<8;i++) dv[i] = fmaxf(ma[i], mc[i]);
            } else {
#pragma unroll
                for (int i=0;i<8;i++) dv[i] = fmaxf(fmaxf(mb[i], ma[i]), mc[i]);
            }
            float4* o = reinterpret_cast<float4*>(dim_ + q * WW + cb);
            o[0] = make_float4(dv[0],dv[1],dv[2],dv[3]);
            o[1] = make_float4(dv[4],dv[5],dv[6],dv[7]);
#pragma unroll
            for (int i=0;i<8;i++) lmax = fmaxf(lmax, dv[i]);
        }
#pragma unroll
        for (int i=0;i<8;i++){ mb[i]=ma[i]; ma[i]=mc[i]; }
        if (p + 1 < Rhi) {
#pragma unroll
            for (int i=0;i<8;i++){ axp[i]=axc[i]; axc[i]=axn[i];
                                   axyp[i]=axyc[i]; axyc[i]=axyn[i];
                                   ayp[i]=ayc[i];  ayc[i]=ayn[i]; }
            if (p + 2 <= HH - 1) COMPUTE_DD(p+2, axn, axyn, ayn);
        }
    }
    if (r1 == HH) {   // bottom image row: dst(H-1) = max(m(H-2), m(H-1))
        float dv[8];
#pragma unroll
        for (int i=0;i<8;i++){ dv[i]=fmaxf(mb[i], ma[i]); lmax = fmaxf(lmax, dv[i]); }
        float4* o = reinterpret_cast<float4*>(dim_ + (HH-1) * WW + cb);
        o[0]=make_float4(dv[0],dv[1],dv[2],dv[3]);
        o[1]=make_float4(dv[4],dv[5],dv[6],dv[7]);
    }
#pragma unroll
    for (int o=16;o;o>>=1) lmax = fmaxf(lmax, __shfl_xor_sync(0xffffffffu, lmax, o));
    if (lane==0) atomicMaxFloat(&g_max[img], lmax);
}

// ---------------------------------------------------------------------------
// Pass B: pointwise mask + lazy conv1x1. out = mask*relu(W x + b) + x,
// mask = 1 if dst>t, 0 if dst<t, x if dst==t;  conv computed only when mask!=0.
// ---------------------------------------------------------------------------
__global__ void fuse_kernel(const float* __restrict__ x, const float* __restrict__ wt,
                            const float* __restrict__ bias, float* __restrict__ out) {
    int t = blockIdx.x * blockDim.x + threadIdx.x;   // one float4 per thread
    int img = t >> 14;                               // 16384 float4 per image
    int off = (t & 16383) << 2;
    size_t base = (size_t)img * HWSZ + off;
    float tthr = 0.7f * g_max[img];                  // THRESH_FRAC
    float4 d4 = *reinterpret_cast<const float4*>(g_dst + base);
    float4 x4 = *reinterpret_cast<const float4*>(x + base);
    float dv[4] = {d4.x,d4.y,d4.z,d4.w};
    float xv[4] = {x4.x,x4.y,x4.z,x4.w};
    float ov[4];
    int b = img >> 6;
    int c = img & 63;
    const float* xch = x + (size_t)(b << 6) * HWSZ + off;  // x[b, ci, pix]
    const float* wr  = wt + (c << 6);
#pragma unroll
    for (int k=0;k<4;k++){
        float o;
        if (dv[k] < tthr) {
            o = xv[k];
        } else {
            float acc = bias[c];
#pragma unroll 8
            for (int ci=0; ci<CCH; ci++) acc = fmaf(wr[ci], xch[ci*HWSZ + k], acc);
            float y = fmaxf(acc, 0.0f);
            float mask = (dv[k] > tthr) ? 1.0f : xv[k];   // tie keeps pixel
            o = fmaf(mask, y, xv[k]);
        }
        ov[k] = o;
    }
    *reinterpret_cast<float4*>(out + base) = make_float4(ov[0],ov[1],ov[2],ov[3]);
}

extern "C" void kernel_launch(void* const* d_in, const int* in_sizes, int n_in,
                              void* d_out, int out_size) {
    const float* x  = (const float*)d_in[0];
    const float* w  = (const float*)d_in[1];
    const float* b  = (const float*)d_in[2];
    float* out = (float*)d_out;
    init_max_kernel<<<2, 256>>>();
    harris_kernel<<<NIMG * 4, 32>>>(x);
    fuse_kernel<<<(NIMG * HWSZ / 4) / 256, 256>>>(x, w, b, out);
}

// round 2
// speedup vs baseline: 1.3019x; 1.3019x over previous
#include <cuda_runtime.h>
#include <math_constants.h>

#define HH 256
#define WW 256
#define NIMG 512          // B*C = 8*64
#define CCH 64
#define HWSZ 65536        // 256*256
#define SEGROWS 16
#define NSEG 16           // 256 / SEGROWS

// Scratch (static device globals — no runtime allocation)
__device__ float g_dst[NIMG * HWSZ];          // dilated Harris response (fp32, exact)
__device__ float g_cmax[NIMG * HH * 16];      // per-(row,16col-chunk) max of dst
__device__ float g_segmax[NIMG * NSEG];       // per-segment max of dst
__device__ float g_tmax[NIMG];                // 0.7 * per-image max

// ---------------------------------------------------------------------------
// Pass A: Harris response R -> 3x3 dilation dst, chunk maxes, out=x copy.
// One warp per (image, 16-row segment). Each lane owns 8 columns (full 256-wide
// row per warp). Sliding windows in registers; lane-boundary exchange via shfl.
// ---------------------------------------------------------------------------

#define LOAD_XROW(r, dst_)  do {                                              \
    int rr__ = (r);                                                           \
    rr__ = (rr__ < 0) ? -rr__ : ((rr__ >= HH) ? (2*HH - 2 - rr__) : rr__);    \
    const float4* p__ = reinterpret_cast<const float4*>(xim + rr__ * WW + cb);\
    float4 q0__ = p__[0], q1__ = p__[1];                                      \
    dst_[0]=q0__.x; dst_[1]=q0__.y; dst_[2]=q0__.z; dst_[3]=q0__.w;           \
    dst_[4]=q1__.x; dst_[5]=q1__.y; dst_[6]=q1__.z; dst_[7]=q1__.w;           \
} while(0)

// Compute gradient-product row (row): dxx,dxy,dyy into AX/AXY/AY. Advances x window.
#define COMPUTE_DD(row, AX, AXY, AY) do {                                     \
    float xc__[8]; LOAD_XROW((row)+1, xc__);                                  \
    float u__[8], v__[8];                                                     \
    _Pragma("unroll")                                                         \
    for (int i=0;i<8;i++){ u__[i] = xa[i] + 2.0f*xb[i] + xc__[i];             \
                           v__[i] = xc__[i] - xa[i]; }                        \
    float uL__ = __shfl_up_sync(0xffffffffu, u__[7], 1);                      \
    float uR__ = __shfl_down_sync(0xffffffffu, u__[0], 1);                    \
    float vL__ = __shfl_up_sync(0xffffffffu, v__[7], 1);                      \
    float vR__ = __shfl_down_sync(0xffffffffu, v__[0], 1);                    \
    if (lane == 0)  { uL__ = u__[1]; vL__ = v__[1]; }                         \
    if (lane == 31) { uR__ = u__[6]; vR__ = v__[6]; }                         \
    _Pragma("unroll")                                                         \
    for (int i=0;i<8;i++){                                                    \
        float um1__ = (i==0)? uL__ : u__[i-1];                                \
        float up1__ = (i==7)? uR__ : u__[i+1];                                \
        float vm1__ = (i==0)? vL__ : v__[i-1];                                \
        float vp1__ = (i==7)? vR__ : v__[i+1];                                \
        float dx__ = (up1__ - um1__) * SC;                                    \
        float dy__ = (vm1__ + 2.0f*v__[i] + vp1__) * SC;                      \
        AX[i] = dx__*dx__; AXY[i] = dx__*dy__; AY[i] = dy__*dy__;             \
    }                                                                         \
    _Pragma("unroll")                                                         \
    for (int i=0;i<8;i++){ xa[i] = xb[i]; xb[i] = xc__[i]; }                  \
} while(0)

// Horizontal sums + R + horiz 3-max + emit dst row q = PV-1 (uses sxx/sxy/syy)
#define EMIT_P(PV) do {                                                       \
    float xxL__ = __shfl_up_sync(0xffffffffu, sxx[7],1);                      \
    float xxR__ = __shfl_down_sync(0xffffffffu, sxx[0],1);                    \
    float xyL__ = __shfl_up_sync(0xffffffffu, sxy[7],1);                      \
    float xyR__ = __shfl_down_sync(0xffffffffu, sxy[0],1);                    \
    float yyL__ = __shfl_up_sync(0xffffffffu, syy[7],1);                      \
    float yyR__ = __shfl_down_sync(0xffffffffu, syy[0],1);                    \
    if (lane==0){  xxL__=sxx[1]; xyL__=sxy[1]; yyL__=syy[1]; }                \
    if (lane==31){ xxR__=sxx[6]; xyR__=sxy[6]; yyR__=syy[6]; }                \
    float Rv__[8];                                                            \
    _Pragma("unroll")                                                         \
    for (int i=0;i<8;i++){                                                    \
        float ixx = ((i==0)?xxL__:sxx[i-1]) + sxx[i] + ((i==7)?xxR__:sxx[i+1]);\
        float ixy = ((i==0)?xyL__:sxy[i-1]) + sxy[i] + ((i==7)?xyR__:sxy[i+1]);\
        float iyy = ((i==0)?yyL__:syy[i-1]) + syy[i] + ((i==7)?yyR__:syy[i+1]);\
        float det = ixx*iyy - ixy*ixy;                                        \
        float tr  = ixx + iyy;                                                \
        Rv__[i] = det - 0.04f * tr * tr;                                      \
    }                                                                         \
    float RL__ = __shfl_up_sync(0xffffffffu, Rv__[7],1);                      \
    float RR__ = __shfl_down_sync(0xffffffffu, Rv__[0],1);                    \
    if (lane==0)  RL__ = -CUDART_INF_F;                                       \
    if (lane==31) RR__ = -CUDART_INF_F;                                       \
    float mc__[8];                                                            \
    _Pragma("unroll")                                                         \
    for (int i=0;i<8;i++){                                                    \
        float l__ = (i==0)?RL__:Rv__[i-1];                                    \
        float r__ = (i==7)?RR__:Rv__[i+1];                                    \
        mc__[i] = fmaxf(fmaxf(l__, Rv__[i]), r__);                            \
    }                                                                         \
    int q__ = (PV) - 1;                                                       \
    if (q__ >= r0) {                                                          \
        float dv__[8];                                                        \
        if (q__ == 0) {                                                       \
            _Pragma("unroll")                                                 \
            for (int i=0;i<8;i++) dv__[i] = fmaxf(ma[i], mc__[i]);            \
        } else {                                                              \
            _Pragma("unroll")                                                 \
            for (int i=0;i<8;i++) dv__[i] = fmaxf(fmaxf(mb[i],ma[i]),mc__[i]);\
        }                                                                     \
        float4* po__ = reinterpret_cast<float4*>(dim_ + q__ * WW + cb);       \
        po__[0] = make_float4(dv__[0],dv__[1],dv__[2],dv__[3]);               \
        po__[1] = make_float4(dv__[4],dv__[5],dv__[6],dv__[7]);               \
        float lm__ = dv__[0];                                                 \
        _Pragma("unroll")                                                     \
        for (int i=1;i<8;i++) lm__ = fmaxf(lm__, dv__[i]);                    \
        float pm__ = fmaxf(lm__, __shfl_xor_sync(0xffffffffu, lm__, 1));      \
        lmax = fmaxf(lmax, pm__);                                             \
        float chv__ = __shfl_sync(0xffffffffu, pm__, (lane*2)&31);            \
        if (lane < 16) g_cmax[((img<<8)+q__)*16 + lane] = chv__;              \
    }                                                                         \
    _Pragma("unroll")                                                         \
    for (int i=0;i<8;i++){ mb[i]=ma[i]; ma[i]=mc__[i]; }                      \
} while(0)

__global__ void __launch_bounds__(32, 14) harris_kernel(const float* __restrict__ x,
                                                        float* __restrict__ out) {
    const int img  = blockIdx.x >> 4;
    const int seg  = blockIdx.x & (NSEG - 1);
    const int lane = threadIdx.x;
    const int cb   = lane * 8;
    const float* __restrict__ xim = x + (size_t)img * HWSZ;
    float* __restrict__ oim = out + (size_t)img * HWSZ;
    float* __restrict__ dim_ = g_dst + (size_t)img * HWSZ;

    const int r0 = seg * SEGROWS;
    const int r1 = r0 + SEGROWS;

    // out = x for this segment's rows (patched later only at rare corners)
    for (int r = r0; r < r1; ++r) {
        const float4* ps = reinterpret_cast<const float4*>(xim + r * WW + cb);
        float4 a0 = ps[0], a1 = ps[1];
        float4* po = reinterpret_cast<float4*>(oim + r * WW + cb);
        po[0] = a0; po[1] = a1;
    }

    const float SC = (1.0f / 12.0f);   // SOBEL_SCALE
    float xa[8], xb[8];
    float p2x[8], p2y[8], p2z[8];      // P2 = dd(p-1)+dd(p)   (xx,xy,yy)
    float cx[8],  cy[8],  cz[8];       // C  = dd(p)
    float ma[8], mb[8];                // horizontal-max windows m(p-1), m(p-2)
    float lmax = -CUDART_INF_F;

#pragma unroll
    for (int i=0;i<8;i++){ ma[i]=0.f; mb[i]=0.f; }

    int Rlo;
    if (r0 == 0) {
        Rlo = 0;
        LOAD_XROW(-1, xa);
        LOAD_XROW(0,  xb);
        COMPUTE_DD(0, cx, cy, cz);
#pragma unroll
        for (int i=0;i<8;i++){ p2x[i]=cx[i]+cx[i]; p2y[i]=cy[i]+cy[i]; p2z[i]=cz[i]+cz[i]; }
    } else {
        Rlo = r0 - 1;
        float d1x[8], d1y[8], d1z[8];
        LOAD_XROW(Rlo - 2, xa);
        LOAD_XROW(Rlo - 1, xb);
        COMPUTE_DD(Rlo - 1, d1x, d1y, d1z);
        COMPUTE_DD(Rlo,     cx, cy, cz);
#pragma unroll
        for (int i=0;i<8;i++){ p2x[i]=d1x[i]+cx[i]; p2y[i]=d1y[i]+cy[i]; p2z[i]=d1z[i]+cz[i]; }
    }

    const int pend = (r1 == HH) ? (HH - 1) : (r1 + 1);
    for (int p = Rlo; p < pend; ++p) {
        float nx[8], ny[8], nz[8];
        COMPUTE_DD(p+1, nx, ny, nz);
        float sxx[8], sxy[8], syy[8];
        if (p == 0) {
#pragma unroll
            for (int i=0;i<8;i++){ sxx[i]=cx[i]+2.0f*nx[i];
                                   sxy[i]=cy[i]+2.0f*ny[i];
                                   syy[i]=cz[i]+2.0f*nz[i]; }
        } else {
#pragma unroll
            for (int i=0;i<8;i++){ sxx[i]=p2x[i]+nx[i];
                                   sxy[i]=p2y[i]+ny[i];
                                   syy[i]=p2z[i]+nz[i]; }
        }
        // rotate state early (frees N before the R stage)
#pragma unroll
        for (int i=0;i<8;i++){ p2x[i]=cx[i]+nx[i]; cx[i]=nx[i];
                               p2y[i]=cy[i]+ny[i]; cy[i]=ny[i];
                               p2z[i]=cz[i]+nz[i]; cz[i]=nz[i]; }
        EMIT_P(p);
    }

    if (r1 == HH) {
        // peel p = 255: vertical sum = dd(254) + dd(255) + reflect(dd(254))
        float sxx[8], sxy[8], syy[8];
#pragma unroll
        for (int i=0;i<8;i++){
            sxx[i] = cx[i] + 2.0f*(p2x[i]-cx[i]);
            sxy[i] = cy[i] + 2.0f*(p2y[i]-cy[i]);
            syy[i] = cz[i] + 2.0f*(p2z[i]-cz[i]);
        }
        EMIT_P(255);
        // bottom image row: dst(255) = max(m(254), m(255))
        float dv[8];
#pragma unroll
        for (int i=0;i<8;i++) dv[i] = fmaxf(mb[i], ma[i]);
        float4* po = reinterpret_cast<float4*>(dim_ + (HH-1) * WW + cb);
        po[0] = make_float4(dv[0],dv[1],dv[2],dv[3]);
        po[1] = make_float4(dv[4],dv[5],dv[6],dv[7]);
        float lm = dv[0];
#pragma unroll
        for (int i=1;i<8;i++) lm = fmaxf(lm, dv[i]);
        float pm = fmaxf(lm, __shfl_xor_sync(0xffffffffu, lm, 1));
        lmax = fmaxf(lmax, pm);
        float chv = __shfl_sync(0xffffffffu, pm, (lane*2)&31);
        if (lane < 16) g_cmax[((img<<8)+(HH-1))*16 + lane] = chv;
    }

#pragma unroll
    for (int o=16;o;o>>=1) lmax = fmaxf(lmax, __shfl_xor_sync(0xffffffffu, lmax, o));
    if (lane == 0) g_segmax[img * NSEG + seg] = lmax;
}

// ---------------------------------------------------------------------------
// Tiny reduce: t = 0.7 * max over segments
// ---------------------------------------------------------------------------
__global__ void reduce_kernel() {
    int img = blockIdx.x * blockDim.x + threadIdx.x;
    if (img < NIMG) {
        float m = -CUDART_INF_F;
#pragma unroll
        for (int i=0;i<NSEG;i++) m = fmaxf(m, g_segmax[img * NSEG + i]);
        g_tmax[img] = 0.7f * m;   // THRESH_FRAC
    }
}

// ---------------------------------------------------------------------------
// Patch: one thread per 16-col chunk. Almost all exit on chunkmax < t.
// Flagged chunks: per-pixel mask + lazy conv1x1, overwrite out.
// ---------------------------------------------------------------------------
__global__ void patch_kernel(const float* __restrict__ x, const float* __restrict__ wt,
                             const float* __restrict__ bias, float* __restrict__ out) {
    int cid = blockIdx.x * blockDim.x + threadIdx.x;   // NIMG*256*16 chunks
    int img = cid >> 12;
    float t = g_tmax[img];
    float cm = g_cmax[cid];
    if (cm < t) return;           // exact: all dst in chunk < t  =>  out stays x

    int rc  = cid & 4095;
    int row = rc >> 4;
    int ch  = rc & 15;
    size_t base = (size_t)img * HWSZ + row * WW + ch * 16;
    int b = img >> 6;
    int c = img & 63;
    const float* wr = wt + (c << 6);
    float bi = bias[c];
    const float* xb0 = x + (size_t)(b << 6) * HWSZ + row * WW + ch * 16;

    for (int k = 0; k < 16; ++k) {
        float d  = g_dst[base + k];
        float xv = x[base + k];
        float o;
        if (d < t) {
            o = xv;
        } else {
            float acc = bi;
#pragma unroll 8
            for (int ci = 0; ci < CCH; ++ci) acc = fmaf(wr[ci], xb0[(size_t)ci * HWSZ + k], acc);
            float y = fmaxf(acc, 0.0f);
            float mask = (d > t) ? 1.0f : xv;   // tie keeps pixel value
            o = fmaf(mask, y, xv);
        }
        out[base + k] = o;
    }
}

extern "C" void kernel_launch(void* const* d_in, const int* in_sizes, int n_in,
                              void* d_out, int out_size) {
    const float* x = (const float*)d_in[0];
    const float* w = (const float*)d_in[1];
    const float* b = (const float*)d_in[2];
    float* out = (float*)d_out;
    harris_kernel<<<NIMG * NSEG, 32>>>(x, out);
    reduce_kernel<<<2, 256>>>();
    patch_kernel<<<(NIMG * HH * 16) / 256, 256>>>(x, w, b, out);
}

// round 4
// speedup vs baseline: 1.8072x; 1.3882x over previous
#include <cuda_runtime.h>
#include <math_constants.h>

#define HH 256
#define WW 256
#define NIMG 512          // B*C = 8*64
#define CCH 64
#define HWSZ 65536        // 256*256
#define SEGROWS 16
#define NSEG 16           // 256 / SEGROWS
#define NCHUNK (NIMG * HH * 16)

// Scratch (static device globals — no runtime allocation)
__device__ float g_cmax[NCHUNK];              // per-(row,16col-chunk) max of dst
__device__ float g_segmax[NIMG * NSEG];       // per-segment max of dst
__device__ float g_tmax[NIMG];                // 0.7 * per-image max
__device__ int   g_list[NCHUNK];              // flagged chunk ids
__device__ int   g_count;

__device__ __forceinline__ int rrow(int r) {
    return r < 0 ? -r : (r >= HH ? 2*HH - 2 - r : r);
}

// clamp dynamic local-array index into [0,4] — prevents speculative
// out-of-frame LDL when ptxas flattens the border branches into selects
#define CL(i) (min(max((int)(i), 0), 4))

// ---------------------------------------------------------------------------
// Pass A: Harris response R -> 3x3 dilation dst (NOT stored), chunk maxes,
// segment maxes, out=x copy. One warp per (image, 16-row segment); lane owns
// 8 columns. All FP contractions pinned with explicit fmaf so the apply
// kernel can recompute dst bit-identically.
// ---------------------------------------------------------------------------

#define LOAD_XROW(r, dst_)  do {                                              \
    int rr__ = (r);                                                           \
    rr__ = (rr__ < 0) ? -rr__ : ((rr__ >= HH) ? (2*HH - 2 - rr__) : rr__);    \
    const float4* p__ = reinterpret_cast<const float4*>(xim + rr__ * WW + cb);\
    float4 q0__ = p__[0], q1__ = p__[1];                                      \
    dst_[0]=q0__.x; dst_[1]=q0__.y; dst_[2]=q0__.z; dst_[3]=q0__.w;           \
    dst_[4]=q1__.x; dst_[5]=q1__.y; dst_[6]=q1__.z; dst_[7]=q1__.w;           \
} while(0)

#define COMPUTE_DD(row, AX, AXY, AY) do {                                     \
    float xc__[8]; LOAD_XROW((row)+1, xc__);                                  \
    float u__[8], v__[8];                                                     \
    _Pragma("unroll")                                                         \
    for (int i=0;i<8;i++){ u__[i] = fmaf(2.0f, xb[i], xa[i]) + xc__[i];       \
                           v__[i] = xc__[i] - xa[i]; }                        \
    float uL__ = __shfl_up_sync(0xffffffffu, u__[7], 1);                      \
    float uR__ = __shfl_down_sync(0xffffffffu, u__[0], 1);                    \
    float vL__ = __shfl_up_sync(0xffffffffu, v__[7], 1);                      \
    float vR__ = __shfl_down_sync(0xffffffffu, v__[0], 1);                    \
    if (lane == 0)  { uL__ = u__[1]; vL__ = v__[1]; }                         \
    if (lane == 31) { uR__ = u__[6]; vR__ = v__[6]; }                         \
    _Pragma("unroll")                                                         \
    for (int i=0;i<8;i++){                                                    \
        float um1__ = (i==0)? uL__ : u__[i-1];                                \
        float up1__ = (i==7)? uR__ : u__[i+1];                                \
        float vm1__ = (i==0)? vL__ : v__[i-1];                                \
        float vp1__ = (i==7)? vR__ : v__[i+1];                                \
        float dx__ = (up1__ - um1__) * SC;                                    \
        float dy__ = (fmaf(2.0f, v__[i], vm1__) + vp1__) * SC;                \
        AX[i] = dx__*dx__; AXY[i] = dx__*dy__; AY[i] = dy__*dy__;             \
    }                                                                         \
    _Pragma("unroll")                                                         \
    for (int i=0;i<8;i++){ xa[i] = xb[i]; xb[i] = xc__[i]; }                  \
} while(0)

// Horizontal sums + R + horiz 3-max + emit dst row q = PV-1 (uses sxx/sxy/syy)
#define EMIT_P(PV) do {                                                       \
    float xxL__ = __shfl_up_sync(0xffffffffu, sxx[7],1);                      \
    float xxR__ = __shfl_down_sync(0xffffffffu, sxx[0],1);                    \
    float xyL__ = __shfl_up_sync(0xffffffffu, sxy[7],1);                      \
    float xyR__ = __shfl_down_sync(0xffffffffu, sxy[0],1);                    \
    float yyL__ = __shfl_up_sync(0xffffffffu, syy[7],1);                      \
    float yyR__ = __shfl_down_sync(0xffffffffu, syy[0],1);                    \
    if (lane==0){  xxL__=sxx[1]; xyL__=sxy[1]; yyL__=syy[1]; }                \
    if (lane==31){ xxR__=sxx[6]; xyR__=sxy[6]; yyR__=syy[6]; }                \
    float Rv__[8];                                                            \
    _Pragma("unroll")                                                         \
    for (int i=0;i<8;i++){                                                    \
        float ixx = (((i==0)?xxL__:sxx[i-1]) + sxx[i]) + ((i==7)?xxR__:sxx[i+1]);\
        float ixy = (((i==0)?xyL__:sxy[i-1]) + sxy[i]) + ((i==7)?xyR__:sxy[i+1]);\
        float iyy = (((i==0)?yyL__:syy[i-1]) + syy[i]) + ((i==7)?yyR__:syy[i+1]);\
        float t1__ = ixy * ixy;                                               \
        float det__ = fmaf(ixx, iyy, -t1__);                                  \
        float tr__  = ixx + iyy;                                              \
        float t2__ = tr__ * tr__;                                             \
        Rv__[i] = fmaf(-0.04f, t2__, det__);                                  \
    }                                                                         \
    float RL__ = __shfl_up_sync(0xffffffffu, Rv__[7],1);                      \
    float RR__ = __shfl_down_sync(0xffffffffu, Rv__[0],1);                    \
    if (lane==0)  RL__ = -CUDART_INF_F;                                       \
    if (lane==31) RR__ = -CUDART_INF_F;                                       \
    float mc__[8];                                                            \
    _Pragma("unroll")                                                         \
    for (int i=0;i<8;i++){                                                    \
        float l__ = (i==0)?RL__:Rv__[i-1];                                    \
        float r__ = (i==7)?RR__:Rv__[i+1];                                    \
        mc__[i] = fmaxf(fmaxf(l__, Rv__[i]), r__);                            \
    }                                                                         \
    int q__ = (PV) - 1;                                                       \
    if (q__ >= r0) {                                                          \
        float dv__[8];                                                        \
        if (q__ == 0) {                                                       \
            _Pragma("unroll")                                                 \
            for (int i=0;i<8;i++) dv__[i] = fmaxf(ma[i], mc__[i]);            \
        } else {                                                              \
            _Pragma("unroll")                                                 \
            for (int i=0;i<8;i++) dv__[i] = fmaxf(fmaxf(mb[i],ma[i]),mc__[i]);\
        }                                                                     \
        float lm__ = dv__[0];                                                 \
        _Pragma("unroll")                                                     \
        for (int i=1;i<8;i++) lm__ = fmaxf(lm__, dv__[i]);                    \
        float pm__ = fmaxf(lm__, __shfl_xor_sync(0xffffffffu, lm__, 1));      \
        lmax = fmaxf(lmax, pm__);                                             \
        float chv__ = __shfl_sync(0xffffffffu, pm__, (lane*2)&31);            \
        if (lane < 16) g_cmax[((img<<8)+q__)*16 + lane] = chv__;              \
    }                                                                         \
    _Pragma("unroll")                                                         \
    for (int i=0;i<8;i++){ mb[i]=ma[i]; ma[i]=mc__[i]; }                      \
} while(0)

__global__ void __launch_bounds__(32, 16) harris_kernel(const float* __restrict__ x,
                                                        float* __restrict__ out) {
    if (blockIdx.x == 0 && threadIdx.x == 0) g_count = 0;   // reset list
    const int img  = blockIdx.x >> 4;
    const int seg  = blockIdx.x & (NSEG - 1);
    const int lane = threadIdx.x;
    const int cb   = lane * 8;
    const float* __restrict__ xim = x + (size_t)img * HWSZ;
    float* __restrict__ oim = out + (size_t)img * HWSZ;

    const int r0 = seg * SEGROWS;
    const int r1 = r0 + SEGROWS;

    // out = x for this segment's rows (patched later only at rare corners)
    for (int r = r0; r < r1; ++r) {
        const float4* ps = reinterpret_cast<const float4*>(xim + r * WW + cb);
        float4 a0 = ps[0], a1 = ps[1];
        float4* po = reinterpret_cast<float4*>(oim + r * WW + cb);
        po[0] = a0; po[1] = a1;
    }

    const float SC = (1.0f / 12.0f);   // SOBEL_SCALE
    float xa[8], xb[8];
    float p2x[8], p2y[8], p2z[8];      // P2 = dd(p-1)+dd(p)   (xx,xy,yy)
    float cx[8],  cy[8],  cz[8];       // C  = dd(p)
    float ma[8], mb[8];                // horizontal-max windows m(p-1), m(p-2)
    float lmax = -CUDART_INF_F;

#pragma unroll
    for (int i=0;i<8;i++){ ma[i]=0.f; mb[i]=0.f; }

    int Rlo;
    if (r0 == 0) {
        Rlo = 0;
        LOAD_XROW(-1, xa);
        LOAD_XROW(0,  xb);
        COMPUTE_DD(0, cx, cy, cz);
#pragma unroll
        for (int i=0;i<8;i++){ p2x[i]=cx[i]+cx[i]; p2y[i]=cy[i]+cy[i]; p2z[i]=cz[i]+cz[i]; }
    } else {
        Rlo = r0 - 1;
        float d1x[8], d1y[8], d1z[8];
        LOAD_XROW(Rlo - 2, xa);
        LOAD_XROW(Rlo - 1, xb);
        COMPUTE_DD(Rlo - 1, d1x, d1y, d1z);
        COMPUTE_DD(Rlo,     cx, cy, cz);
#pragma unroll
        for (int i=0;i<8;i++){ p2x[i]=d1x[i]+cx[i]; p2y[i]=d1y[i]+cy[i]; p2z[i]=d1z[i]+cz[i]; }
    }

    const int pend = (r1 == HH) ? (HH - 1) : (r1 + 1);
    for (int p = Rlo; p < pend; ++p) {
        float nx[8], ny[8], nz[8];
        COMPUTE_DD(p+1, nx, ny, nz);
        float sxx[8], sxy[8], syy[8];
        if (p == 0) {
#pragma unroll
            for (int i=0;i<8;i++){ sxx[i]=fmaf(2.0f, nx[i], cx[i]);
                                   sxy[i]=fmaf(2.0f, ny[i], cy[i]);
                                   syy[i]=fmaf(2.0f, nz[i], cz[i]); }
        } else {
#pragma unroll
            for (int i=0;i<8;i++){ sxx[i]=p2x[i]+nx[i];
                                   sxy[i]=p2y[i]+ny[i];
                                   syy[i]=p2z[i]+nz[i]; }
        }
#pragma unroll
        for (int i=0;i<8;i++){ p2x[i]=cx[i]+nx[i]; cx[i]=nx[i];
                               p2y[i]=cy[i]+ny[i]; cy[i]=ny[i];
                               p2z[i]=cz[i]+nz[i]; cz[i]=nz[i]; }
        EMIT_P(p);
    }

    if (r1 == HH) {
        // peel p = 255: vertical sum = dd(255) + 2*(p2-dd(255)) (= +2*dd(254))
        float sxx[8], sxy[8], syy[8];
#pragma unroll
        for (int i=0;i<8;i++){
            sxx[i] = fmaf(2.0f, p2x[i] - cx[i], cx[i]);
            sxy[i] = fmaf(2.0f, p2y[i] - cy[i], cy[i]);
            syy[i] = fmaf(2.0f, p2z[i] - cz[i], cz[i]);
        }
        EMIT_P(255);
        // bottom image row: dst(255) = max(m(254), m(255))
        float dv[8];
#pragma unroll
        for (int i=0;i<8;i++) dv[i] = fmaxf(mb[i], ma[i]);
        float lm = dv[0];
#pragma unroll
        for (int i=1;i<8;i++) lm = fmaxf(lm, dv[i]);
        float pm = fmaxf(lm, __shfl_xor_sync(0xffffffffu, lm, 1));
        lmax = fmaxf(lmax, pm);
        float chv = __shfl_sync(0xffffffffu, pm, (lane*2)&31);
        if (lane < 16) g_cmax[((img<<8)+(HH-1))*16 + lane] = chv;
    }

#pragma unroll
    for (int o=16;o;o>>=1) lmax = fmaxf(lmax, __shfl_xor_sync(0xffffffffu, lmax, o));
    if (lane == 0) g_segmax[img * NSEG + seg] = lmax;
}

// ---------------------------------------------------------------------------
// Scan: compute t per image, compact flagged chunks (cmax >= t) into g_list.
// Block handles 256 chunks of one image. 8192 blocks x 256.
// ---------------------------------------------------------------------------
__global__ void scan_kernel() {
    __shared__ float s16[16];
    int img = blockIdx.x >> 4;
    if (threadIdx.x < 16) s16[threadIdx.x] = g_segmax[img * NSEG + threadIdx.x];
    __syncthreads();
    float m = s16[0];
#pragma unroll
    for (int i=1;i<16;i++) m = fmaxf(m, s16[i]);
    float t = 0.7f * m;   // THRESH_FRAC
    if ((blockIdx.x & 15) == 0 && threadIdx.x == 0) g_tmax[img] = t;
    int cid = (img << 12) + ((blockIdx.x & 15) << 8) + threadIdx.x;
    if (g_cmax[cid] >= t) {
        int p = atomicAdd(&g_count, 1);
        g_list[p] = cid;
    }
}

// ---------------------------------------------------------------------------
// Apply: one warp per flagged chunk. Recompute dst (bit-identical to pass A),
// then lane-parallel conv1x1 for flagged pixels; overwrite out.
// Lane l owns field column c = c0-2+l (l=0..19 meaningful).
// ---------------------------------------------------------------------------
__global__ void apply_kernel(const float* __restrict__ x, const float* __restrict__ wt,
                             const float* __restrict__ bias, float* __restrict__ out) {
    const int gwarp  = (blockIdx.x * blockDim.x + threadIdx.x) >> 5;
    const int nwarps = (gridDim.x * blockDim.x) >> 5;
    const int lane = threadIdx.x & 31;
    const float SC = (1.0f / 12.0f);
    const int total = g_count;

    for (int li = gwarp; li < total; li += nwarps) {
        int cid = g_list[li];
        int img = cid >> 12;
        int rc  = cid & 4095;
        int q   = rc >> 4;
        int c0  = (rc & 15) << 4;
        float t = g_tmax[img];
        const float* __restrict__ xim = x + (size_t)img * HWSZ;

        int c  = c0 - 2 + lane;                 // field column
        int cc = (c < 0) ? -c : (c >= WW ? 2*WW - 2 - c : c);
        int cL = (cc == 0) ? 1 : cc - 1;        // reflect-101 col for x loads
        int cR = (cc == WW-1) ? WW-2 : cc + 1;

        int dlo = q - 2 < 0 ? 0 : q - 2;
        int dhi = q + 2 > HH-1 ? HH-1 : q + 2;

        float ddx[5], ddxy[5], ddy2[5];
        {
            int ra = rrow(dlo - 1) * WW, rb = rrow(dlo) * WW;
            float xaL = xim[ra + cL], xaC = xim[ra + cc], xaR = xim[ra + cR];
            float xbL = xim[rb + cL], xbC = xim[rb + cc], xbR = xim[rb + cR];
            for (int d = dlo; d <= dhi; ++d) {
                int rn = rrow(d + 1) * WW;
                float xcL = xim[rn + cL], xcC = xim[rn + cc], xcR = xim[rn + cR];
                float uL = fmaf(2.0f, xbL, xaL) + xcL;
                float uR = fmaf(2.0f, xbR, xaR) + xcR;
                float vL = xcL - xaL;
                float vC = xcC - xaC;
                float vR = xcR - xaR;
                float dx = (uR - uL) * SC;
                float dy = (fmaf(2.0f, vC, vL) + vR) * SC;
                ddx[CL(d - dlo)]  = dx * dx;
                ddxy[CL(d - dlo)] = dx * dy;
                ddy2[CL(d - dlo)] = dy * dy;
                xaL = xbL; xaC = xbC; xaR = xbR;
                xbL = xcL; xbC = xcC; xbR = xcR;
            }
        }
        float xq = xim[q * WW + cc];            // x at (q, cc) for the mask

        float dstv = -CUDART_INF_F;
        for (int rr = q - 1; rr <= q + 1; ++rr) {
            if (rr < 0 || rr > HH - 1) continue;
            float sxx, sxy, syy;
            if (rr == 0) {
                sxx = fmaf(2.0f, ddx[CL(1 - dlo)],  ddx[CL(0 - dlo)]);
                sxy = fmaf(2.0f, ddxy[CL(1 - dlo)], ddxy[CL(0 - dlo)]);
                syy = fmaf(2.0f, ddy2[CL(1 - dlo)], ddy2[CL(0 - dlo)]);
            } else if (rr == HH - 1) {
                float p2a = ddx[CL(254 - dlo)]  + ddx[CL(255 - dlo)];
                float p2b = ddxy[CL(254 - dlo)] + ddxy[CL(255 - dlo)];
                float p2c = ddy2[CL(254 - dlo)] + ddy2[CL(255 - dlo)];
                sxx = fmaf(2.0f, p2a - ddx[CL(255 - dlo)],  ddx[CL(255 - dlo)]);
                sxy = fmaf(2.0f, p2b - ddxy[CL(255 - dlo)], ddxy[CL(255 - dlo)]);
                syy = fmaf(2.0f, p2c - ddy2[CL(255 - dlo)], ddy2[CL(255 - dlo)]);
            } else {
                sxx = (ddx[CL(rr - 1 - dlo)]  + ddx[CL(rr - dlo)])  + ddx[CL(rr + 1 - dlo)];
                sxy = (ddxy[CL(rr - 1 - dlo)] + ddxy[CL(rr - dlo)]) + ddxy[CL(rr + 1 - dlo)];
                syy = (ddy2[CL(rr - 1 - dlo)] + ddy2[CL(rr - dlo)]) + ddy2[CL(rr + 1 - dlo)];
            }
            float xxm = __shfl_up_sync(0xffffffffu, sxx, 1);
            float xxp = __shfl_down_sync(0xffffffffu, sxx, 1);
            float xym = __shfl_up_sync(0xffffffffu, sxy, 1);
            float xyp = __shfl_down_sync(0xffffffffu, sxy, 1);
            float yym = __shfl_up_sync(0xffffffffu, syy, 1);
            float yyp = __shfl_down_sync(0xffffffffu, syy, 1);
            float ixx = (xxm + sxx) + xxp;
            float ixy = (xym + sxy) + xyp;
            float iyy = (yym + syy) + yyp;
            float t1 = ixy * ixy;
            float det = fmaf(ixx, iyy, -t1);
            float tr  = ixx + iyy;
            float t2 = tr * tr;
            float Rv = fmaf(-0.04f, t2, det);
            if (c < 0 || c > WW - 1) Rv = -CUDART_INF_F;   // dilation clips
            float Rm = __shfl_up_sync(0xffffffffu, Rv, 1);
            float Rp = __shfl_down_sync(0xffffffffu, Rv, 1);
            float mm = fmaxf(fmaxf(Rm, Rv), Rp);
            dstv = fmaxf(dstv, mm);
        }

        bool flg = (lane >= 2) && (lane < 18) && (dstv >= t);
        unsigned bal = __ballot_sync(0xffffffffu, flg);
        if (bal) {
            int b   = img >> 6;
            int cch = img & 63;
            float w0 = wt[(cch << 6) + 2*lane];
            float w1 = wt[(cch << 6) + 2*lane + 1];
            float bi = bias[cch];
            const float* xbase = x + (size_t)(b << 6) * HWSZ;
            while (bal) {
                int lp = __ffs(bal) - 1; bal &= bal - 1;
                int pix = (q << 8) + c0 + lp - 2;
                float xv0 = xbase[(size_t)(2*lane)     * HWSZ + pix];
                float xv1 = xbase[(size_t)(2*lane + 1) * HWSZ + pix];
                float acc = fmaf(w0, xv0, w1 * xv1);
#pragma unroll
                for (int o = 16; o; o >>= 1)
                    acc += __shfl_xor_sync(0xffffffffu, acc, o);
                if (lane == lp) {
                    float y = fmaxf(acc + bi, 0.0f);
                    float mask = (dstv > t) ? 1.0f : xq;   // tie keeps pixel
                    out[(size_t)img * HWSZ + pix] = fmaf(mask, y, xq);
                }
            }
        }
    }
}

extern "C" void kernel_launch(void* const* d_in, const int* in_sizes, int n_in,
                              void* d_out, int out_size) {
    const float* x = (const float*)d_in[0];
    const float* w = (const float*)d_in[1];
    const float* b = (const float*)d_in[2];
    float* out = (float*)d_out;
    harris_kernel<<<NIMG * NSEG, 32>>>(x, out);
    scan_kernel<<<NIMG * 16, 256>>>();
    apply_kernel<<<1184, 256>>>(x, w, b, out);
}

// round 5
// speedup vs baseline: 1.8077x; 1.0003x over previous
#include <cuda_runtime.h>
#include <math_constants.h>

#define HH 256
#define WW 256
#define NIMG 512          // B*C = 8*64
#define CCH 64
#define HWSZ 65536        // 256*256
#define SEGROWS 16
#define NSEG 16           // 256 / SEGROWS

// Scratch (static device globals — no runtime allocation)
__device__ float g_cmax32[NIMG * HH * 32];    // per-(row, lane=8col) max of dst
__device__ float g_segmax[NIMG * NSEG];       // per-segment max of dst

__device__ __forceinline__ int rrow(int r) {
    return r < 0 ? -r : (r >= HH ? 2*HH - 2 - r : r);
}

// clamp dynamic local-array index into [0,4] — prevents speculative
// out-of-frame LDL when ptxas flattens the border branches into selects
#define CL(i) (min(max((int)(i), 0), 4))

// ---------------------------------------------------------------------------
// Pass A: Harris response R -> 3x3 dilation dst (NOT stored), per-lane chunk
// maxes, segment maxes, out=x copy. One warp per (image, 16-row segment);
// lane owns 8 columns. All FP contractions pinned with explicit fmaf so the
// apply path can recompute dst bit-identically.
// ---------------------------------------------------------------------------

#define LOAD_XROW(r, dst_)  do {                                              \
    int rr__ = (r);                                                           \
    rr__ = (rr__ < 0) ? -rr__ : ((rr__ >= HH) ? (2*HH - 2 - rr__) : rr__);    \
    const float4* p__ = reinterpret_cast<const float4*>(xim + rr__ * WW + cb);\
    float4 q0__ = p__[0], q1__ = p__[1];                                      \
    dst_[0]=q0__.x; dst_[1]=q0__.y; dst_[2]=q0__.z; dst_[3]=q0__.w;           \
    dst_[4]=q1__.x; dst_[5]=q1__.y; dst_[6]=q1__.z; dst_[7]=q1__.w;           \
} while(0)

#define COMPUTE_DD(row, AX, AXY, AY) do {                                     \
    float xc__[8]; LOAD_XROW((row)+1, xc__);                                  \
    float u__[8], v__[8];                                                     \
    _Pragma("unroll")                                                         \
    for (int i=0;i<8;i++){ u__[i] = fmaf(2.0f, xb[i], xa[i]) + xc__[i];       \
                           v__[i] = xc__[i] - xa[i]; }                        \
    float uL__ = __shfl_up_sync(0xffffffffu, u__[7], 1);                      \
    float uR__ = __shfl_down_sync(0xffffffffu, u__[0], 1);                    \
    float vL__ = __shfl_up_sync(0xffffffffu, v__[7], 1);                      \
    float vR__ = __shfl_down_sync(0xffffffffu, v__[0], 1);                    \
    if (lane == 0)  { uL__ = u__[1]; vL__ = v__[1]; }                         \
    if (lane == 31) { uR__ = u__[6]; vR__ = v__[6]; }                         \
    _Pragma("unroll")                                                         \
    for (int i=0;i<8;i++){                                                    \
        float um1__ = (i==0)? uL__ : u__[i-1];                                \
        float up1__ = (i==7)? uR__ : u__[i+1];                                \
        float vm1__ = (i==0)? vL__ : v__[i-1];                                \
        float vp1__ = (i==7)? vR__ : v__[i+1];                                \
        float dx__ = (up1__ - um1__) * SC;                                    \
        float dy__ = (fmaf(2.0f, v__[i], vm1__) + vp1__) * SC;                \
        AX[i] = dx__*dx__; AXY[i] = dx__*dy__; AY[i] = dy__*dy__;             \
    }                                                                         \
    _Pragma("unroll")                                                         \
    for (int i=0;i<8;i++){ xa[i] = xb[i]; xb[i] = xc__[i]; }                  \
} while(0)

// Horizontal sums + R + horiz 3-max + emit dst row q = PV-1 (uses sxx/sxy/syy).
// mb is initialized to -inf so dv = max(mb,ma,mc) is uniform (top clip free).
#define EMIT_P(PV) do {                                                       \
    float xxL__ = __shfl_up_sync(0xffffffffu, sxx[7],1);                      \
    float xxR__ = __shfl_down_sync(0xffffffffu, sxx[0],1);                    \
    float xyL__ = __shfl_up_sync(0xffffffffu, sxy[7],1);                      \
    float xyR__ = __shfl_down_sync(0xffffffffu, sxy[0],1);                    \
    float yyL__ = __shfl_up_sync(0xffffffffu, syy[7],1);                      \
    float yyR__ = __shfl_down_sync(0xffffffffu, syy[0],1);                    \
    if (lane==0){  xxL__=sxx[1]; xyL__=sxy[1]; yyL__=syy[1]; }                \
    if (lane==31){ xxR__=sxx[6]; xyR__=sxy[6]; yyR__=syy[6]; }                \
    float Rv__[8];                                                            \
    _Pragma("unroll")                                                         \
    for (int i=0;i<8;i++){                                                    \
        float ixx = (((i==0)?xxL__:sxx[i-1]) + sxx[i]) + ((i==7)?xxR__:sxx[i+1]);\
        float ixy = (((i==0)?xyL__:sxy[i-1]) + sxy[i]) + ((i==7)?xyR__:sxy[i+1]);\
        float iyy = (((i==0)?yyL__:syy[i-1]) + syy[i]) + ((i==7)?yyR__:syy[i+1]);\
        float t1__ = ixy * ixy;                                               \
        float det__ = fmaf(ixx, iyy, -t1__);                                  \
        float tr__  = ixx + iyy;                                              \
        float t2__ = tr__ * tr__;                                             \
        Rv__[i] = fmaf(-0.04f, t2__, det__);                                  \
    }                                                                         \
    float RL__ = __shfl_up_sync(0xffffffffu, Rv__[7],1);                      \
    float RR__ = __shfl_down_sync(0xffffffffu, Rv__[0],1);                    \
    if (lane==0)  RL__ = -CUDART_INF_F;                                       \
    if (lane==31) RR__ = -CUDART_INF_F;                                       \
    float mc__[8];                                                            \
    _Pragma("unroll")                                                         \
    for (int i=0;i<8;i++){                                                    \
        float l__ = (i==0)?RL__:Rv__[i-1];                                    \
        float r__ = (i==7)?RR__:Rv__[i+1];                                    \
        mc__[i] = fmaxf(fmaxf(l__, Rv__[i]), r__);                            \
    }                                                                         \
    int q__ = (PV) - 1;                                                       \
    if (q__ >= r0) {                                                          \
        float lm__ = fmaxf(fmaxf(mb[0],ma[0]),mc__[0]);                       \
        _Pragma("unroll")                                                     \
        for (int i=1;i<8;i++)                                                 \
            lm__ = fmaxf(lm__, fmaxf(fmaxf(mb[i],ma[i]),mc__[i]));            \
        lmax = fmaxf(lmax, lm__);                                             \
        g_cmax32[((img<<8)+q__)*32 + lane] = lm__;                            \
    }                                                                         \
    _Pragma("unroll")                                                         \
    for (int i=0;i<8;i++){ mb[i]=ma[i]; ma[i]=mc__[i]; }                      \
} while(0)

__global__ void __launch_bounds__(32, 16) harris_kernel(const float* __restrict__ x,
                                                        float* __restrict__ out) {
    const int img  = blockIdx.x >> 4;
    const int seg  = blockIdx.x & (NSEG - 1);
    const int lane = threadIdx.x;
    const int cb   = lane * 8;
    const float* __restrict__ xim = x + (size_t)img * HWSZ;
    float* __restrict__ oim = out + (size_t)img * HWSZ;

    const int r0 = seg * SEGROWS;
    const int r1 = r0 + SEGROWS;

    // out = x for this segment's rows (patched later only at rare corners)
    for (int r = r0; r < r1; ++r) {
        const float4* ps = reinterpret_cast<const float4*>(xim + r * WW + cb);
        float4 a0 = ps[0], a1 = ps[1];
        float4* po = reinterpret_cast<float4*>(oim + r * WW + cb);
        po[0] = a0; po[1] = a1;
    }

    const float SC = (1.0f / 12.0f);   // SOBEL_SCALE
    float xa[8], xb[8];
    float p2x[8], p2y[8], p2z[8];      // P2 = dd(p-1)+dd(p)   (xx,xy,yy)
    float cx[8],  cy[8],  cz[8];       // C  = dd(p)
    float ma[8], mb[8];                // horizontal-max windows m(p-1), m(p-2)
    float lmax = -CUDART_INF_F;

#pragma unroll
    for (int i=0;i<8;i++){ ma[i] = -CUDART_INF_F; mb[i] = -CUDART_INF_F; }

    int pstart;
    if (r0 == 0) {
        LOAD_XROW(-1, xa);
        LOAD_XROW(0,  xb);
        COMPUTE_DD(0, cx, cy, cz);
#pragma unroll
        for (int i=0;i<8;i++){ p2x[i]=cx[i]+cx[i]; p2y[i]=cy[i]+cy[i]; p2z[i]=cz[i]+cz[i]; }
        // peeled p == 0 iteration (emits q=-1: nothing; shifts ma/mb)
        {
            float nx[8], ny[8], nz[8];
            COMPUTE_DD(1, nx, ny, nz);
            float sxx[8], sxy[8], syy[8];
#pragma unroll
            for (int i=0;i<8;i++){ sxx[i]=fmaf(2.0f, nx[i], cx[i]);
                                   sxy[i]=fmaf(2.0f, ny[i], cy[i]);
                                   syy[i]=fmaf(2.0f, nz[i], cz[i]); }
#pragma unroll
            for (int i=0;i<8;i++){ p2x[i]=cx[i]+nx[i]; cx[i]=nx[i];
                                   p2y[i]=cy[i]+ny[i]; cy[i]=ny[i];
                                   p2z[i]=cz[i]+nz[i]; cz[i]=nz[i]; }
            EMIT_P(0);
        }
        pstart = 1;
    } else {
        float d1x[8], d1y[8], d1z[8];
        LOAD_XROW(r0 - 3, xa);
        LOAD_XROW(r0 - 2, xb);
        COMPUTE_DD(r0 - 2, d1x, d1y, d1z);
        COMPUTE_DD(r0 - 1, cx, cy, cz);
#pragma unroll
        for (int i=0;i<8;i++){ p2x[i]=d1x[i]+cx[i]; p2y[i]=d1y[i]+cy[i]; p2z[i]=d1z[i]+cz[i]; }
        pstart = r0 - 1;
    }

    const int pend = (r1 == HH) ? (HH - 1) : (r1 + 1);
#pragma unroll 2
    for (int p = pstart; p < pend; ++p) {
        float nx[8], ny[8], nz[8];
        COMPUTE_DD(p+1, nx, ny, nz);
        float sxx[8], sxy[8], syy[8];
#pragma unroll
        for (int i=0;i<8;i++){ sxx[i]=p2x[i]+nx[i];
                               sxy[i]=p2y[i]+ny[i];
                               syy[i]=p2z[i]+nz[i]; }
#pragma unroll
        for (int i=0;i<8;i++){ p2x[i]=cx[i]+nx[i]; cx[i]=nx[i];
                               p2y[i]=cy[i]+ny[i]; cy[i]=ny[i];
                               p2z[i]=cz[i]+nz[i]; cz[i]=nz[i]; }
        EMIT_P(p);
    }

    if (r1 == HH) {
        // peel p = 255: vertical sum = dd(255) + 2*(p2-dd(255)) (= +2*dd(254))
        float sxx[8], sxy[8], syy[8];
#pragma unroll
        for (int i=0;i<8;i++){
            sxx[i] = fmaf(2.0f, p2x[i] - cx[i], cx[i]);
            sxy[i] = fmaf(2.0f, p2y[i] - cy[i], cy[i]);
            syy[i] = fmaf(2.0f, p2z[i] - cz[i], cz[i]);
        }
        EMIT_P(255);
        // bottom image row: dst(255) = max(m(254), m(255))
        float lm = fmaxf(mb[0], ma[0]);
#pragma unroll
        for (int i=1;i<8;i++) lm = fmaxf(lm, fmaxf(mb[i], ma[i]));
        lmax = fmaxf(lmax, lm);
        g_cmax32[((img<<8)+(HH-1))*32 + lane] = lm;
    }

#pragma unroll
    for (int o=16;o;o>>=1) lmax = fmaxf(lmax, __shfl_xor_sync(0xffffffffu, lmax, o));
    if (lane == 0) g_segmax[img * NSEG + seg] = lmax;
}

// ---------------------------------------------------------------------------
// Detect + apply (merged): block covers 256 chunks (16-col each) of one image.
// Computes t from segment maxes, ballots flagged chunks, and the warp
// processes each flagged chunk inline: recompute dst bit-identically, then
// lane-parallel conv1x1 for flagged pixels; overwrite out.
// ---------------------------------------------------------------------------
__global__ void detect_apply_kernel(const float* __restrict__ x, const float* __restrict__ wt,
                                    const float* __restrict__ bias, float* __restrict__ out) {
    __shared__ float s16[16];
    const int img = blockIdx.x >> 4;
    if (threadIdx.x < 16) s16[threadIdx.x] = g_segmax[img * NSEG + threadIdx.x];
    __syncthreads();
    float m = s16[0];
#pragma unroll
    for (int i=1;i<16;i++) m = fmaxf(m, s16[i]);
    const float t = 0.7f * m;   // THRESH_FRAC

    const int lane = threadIdx.x & 31;
    const int mycid = (blockIdx.x << 8) + threadIdx.x;   // global chunk id
    float cm = fmaxf(g_cmax32[2*mycid], g_cmax32[2*mycid + 1]);
    unsigned bal0 = __ballot_sync(0xffffffffu, cm >= t);
    if (!bal0) return;

    const int cidbase = (blockIdx.x << 8) + (threadIdx.x & ~31);
    const float SC = (1.0f / 12.0f);
    const float* __restrict__ xim = x + (size_t)img * HWSZ;

    while (bal0) {
        int chlane = __ffs(bal0) - 1; bal0 &= bal0 - 1;
        int cid = cidbase + chlane;
        int rc  = cid & 4095;
        int q   = rc >> 4;
        int c0  = (rc & 15) << 4;

        int c  = c0 - 2 + lane;                 // field column
        int cc = (c < 0) ? -c : (c >= WW ? 2*WW - 2 - c : c);
        int cL = (cc == 0) ? 1 : cc - 1;        // reflect-101 col for x loads
        int cR = (cc == WW-1) ? WW-2 : cc + 1;

        int dlo = q - 2 < 0 ? 0 : q - 2;
        int dhi = q + 2 > HH-1 ? HH-1 : q + 2;

        float ddx[5], ddxy[5], ddy2[5];
        {
            int ra = rrow(dlo - 1) * WW, rb = rrow(dlo) * WW;
            float xaL = xim[ra + cL], xaC = xim[ra + cc], xaR = xim[ra + cR];
            float xbL = xim[rb + cL], xbC = xim[rb + cc], xbR = xim[rb + cR];
            for (int d = dlo; d <= dhi; ++d) {
                int rn = rrow(d + 1) * WW;
                float xcL = xim[rn + cL], xcC = xim[rn + cc], xcR = xim[rn + cR];
                float uL = fmaf(2.0f, xbL, xaL) + xcL;
                float uR = fmaf(2.0f, xbR, xaR) + xcR;
                float vL = xcL - xaL;
                float vC = xcC - xaC;
                float vR = xcR - xaR;
                float dx = (uR - uL) * SC;
                float dy = (fmaf(2.0f, vC, vL) + vR) * SC;
                ddx[CL(d - dlo)]  = dx * dx;
                ddxy[CL(d - dlo)] = dx * dy;
                ddy2[CL(d - dlo)] = dy * dy;
                xaL = xbL; xaC = xbC; xaR = xbR;
                xbL = xcL; xbC = xcC; xbR = xcR;
            }
        }
        float xq = xim[q * WW + cc];            // x at (q, cc) for the mask

        float dstv = -CUDART_INF_F;
        for (int rr = q - 1; rr <= q + 1; ++rr) {
            if (rr < 0 || rr > HH - 1) continue;
            float sxx, sxy, syy;
            if (rr == 0) {
                sxx = fmaf(2.0f, ddx[CL(1 - dlo)],  ddx[CL(0 - dlo)]);
                sxy = fmaf(2.0f, ddxy[CL(1 - dlo)], ddxy[CL(0 - dlo)]);
                syy = fmaf(2.0f, ddy2[CL(1 - dlo)], ddy2[CL(0 - dlo)]);
            } else if (rr == HH - 1) {
                float p2a = ddx[CL(254 - dlo)]  + ddx[CL(255 - dlo)];
                float p2b = ddxy[CL(254 - dlo)] + ddxy[CL(255 - dlo)];
                float p2c = ddy2[CL(254 - dlo)] + ddy2[CL(255 - dlo)];
                sxx = fmaf(2.0f, p2a - ddx[CL(255 - dlo)],  ddx[CL(255 - dlo)]);
                sxy = fmaf(2.0f, p2b - ddxy[CL(255 - dlo)], ddxy[CL(255 - dlo)]);
                syy = fmaf(2.0f, p2c - ddy2[CL(255 - dlo)], ddy2[CL(255 - dlo)]);
            } else {
                sxx = (ddx[CL(rr - 1 - dlo)]  + ddx[CL(rr - dlo)])  + ddx[CL(rr + 1 - dlo)];
                sxy = (ddxy[CL(rr - 1 - dlo)] + ddxy[CL(rr - dlo)]) + ddxy[CL(rr + 1 - dlo)];
                syy = (ddy2[CL(rr - 1 - dlo)] + ddy2[CL(rr - dlo)]) + ddy2[CL(rr + 1 - dlo)];
            }
            float xxm = __shfl_up_sync(0xffffffffu, sxx, 1);
            float xxp = __shfl_down_sync(0xffffffffu, sxx, 1);
            float xym = __shfl_up_sync(0xffffffffu, sxy, 1);
            float xyp = __shfl_down_sync(0xffffffffu, sxy, 1);
            float yym = __shfl_up_sync(0xffffffffu, syy, 1);
            float yyp = __shfl_down_sync(0xffffffffu, syy, 1);
            float ixx = (xxm + sxx) + xxp;
            float ixy = (xym + sxy) + xyp;
            float iyy = (yym + syy) + yyp;
            float t1 = ixy * ixy;
            float det = fmaf(ixx, iyy, -t1);
            float tr  = ixx + iyy;
            float t2 = tr * tr;
            float Rv = fmaf(-0.04f, t2, det);
            if (c < 0 || c > WW - 1) Rv = -CUDART_INF_F;   // dilation clips
            float Rm = __shfl_up_sync(0xffffffffu, Rv, 1);
            float Rp = __shfl_down_sync(0xffffffffu, Rv, 1);
            float mm = fmaxf(fmaxf(Rm, Rv), Rp);
            dstv = fmaxf(dstv, mm);
        }

        bool flg = (lane >= 2) && (lane < 18) && (dstv >= t);
        unsigned bal = __ballot_sync(0xffffffffu, flg);
        if (bal) {
            int b   = img >> 6;
            int cch = img & 63;
            float w0 = wt[(cch << 6) + 2*lane];
            float w1 = wt[(cch << 6) + 2*lane + 1];
            float bi = bias[cch];
            const float* xbase = x + (size_t)(b << 6) * HWSZ;
            while (bal) {
                int lp = __ffs(bal) - 1; bal &= bal - 1;
                int pix = (q << 8) + c0 + lp - 2;
                float xv0 = xbase[(size_t)(2*lane)     * HWSZ + pix];
                float xv1 = xbase[(size_t)(2*lane + 1) * HWSZ + pix];
                float acc = fmaf(w0, xv0, w1 * xv1);
#pragma unroll
                for (int o = 16; o; o >>= 1)
                    acc += __shfl_xor_sync(0xffffffffu, acc, o);
                if (lane == lp) {
                    float y = fmaxf(acc + bi, 0.0f);
                    float mask = (dstv > t) ? 1.0f : xq;   // tie keeps pixel
                    out[(size_t)img * HWSZ + pix] = fmaf(mask, y, xq);
                }
            }
        }
    }
}

extern "C" void kernel_launch(void* const* d_in, const int* in_sizes, int n_in,
                              void* d_out, int out_size) {
    const float* x = (const float*)d_in[0];
    const float* w = (const float*)d_in[1];
    const float* b = (const float*)d_in[2];
    float* out = (float*)d_out;
    harris_kernel<<<NIMG * NSEG, 32>>>(x, out);
    detect_apply_kernel<<<NIMG * 16, 256>>>(x, w, b, out);
}

// round 6
// speedup vs baseline: 2.1389x; 1.1832x over previous
#include <cuda_runtime.h>
#include <math_constants.h>

#define HH 256
#define WW 256
#define NIMG 512          // B*C = 8*64
#define CCH 64
#define HWSZ 65536        // 256*256
#define SEGROWS 16
#define NSEG 16           // 256 / SEGROWS
#define NCHUNK (NIMG * HH * 16)

// Scratch (static device globals — no runtime allocation)
__device__ float g_cmax32[NIMG * HH * 32];    // per-(row, lane=8col) max of dst
__device__ float g_segmax[NIMG * NSEG];       // per-segment max of dst
__device__ float g_tmax[NIMG];                // 0.7 * per-image max
__device__ int   g_list[NCHUNK];              // flagged chunk ids
__device__ int   g_count;

__device__ __forceinline__ int rrow(int r) {
    return r < 0 ? -r : (r >= HH ? 2*HH - 2 - r : r);
}

// clamp dynamic local-array index into [0,4] — prevents speculative
// out-of-frame LDL when ptxas flattens the border branches into selects
#define CL(i) (min(max((int)(i), 0), 4))

// ---------------------------------------------------------------------------
// Pass A: Harris response R -> 3x3 dilation dst (NOT stored), per-lane chunk
// maxes, segment maxes, out=x copy. One warp per (image, 16-row segment);
// lane owns 8 columns. All FP contractions pinned with explicit fmaf so the
// apply kernel can recompute dst bit-identically.
// ---------------------------------------------------------------------------

#define LOAD_XROW(r, dst_)  do {                                              \
    int rr__ = (r);                                                           \
    rr__ = (rr__ < 0) ? -rr__ : ((rr__ >= HH) ? (2*HH - 2 - rr__) : rr__);    \
    const float4* p__ = reinterpret_cast<const float4*>(xim + rr__ * WW + cb);\
    float4 q0__ = p__[0], q1__ = p__[1];                                      \
    dst_[0]=q0__.x; dst_[1]=q0__.y; dst_[2]=q0__.z; dst_[3]=q0__.w;           \
    dst_[4]=q1__.x; dst_[5]=q1__.y; dst_[6]=q1__.z; dst_[7]=q1__.w;           \
} while(0)

#define COMPUTE_DD(row, AX, AXY, AY) do {                                     \
    float xc__[8]; LOAD_XROW((row)+1, xc__);                                  \
    float u__[8], v__[8];                                                     \
    _Pragma("unroll")                                                         \
    for (int i=0;i<8;i++){ u__[i] = fmaf(2.0f, xb[i], xa[i]) + xc__[i];       \
                           v__[i] = xc__[i] - xa[i]; }                        \
    float uL__ = __shfl_up_sync(0xffffffffu, u__[7], 1);                      \
    float uR__ = __shfl_down_sync(0xffffffffu, u__[0], 1);                    \
    float vL__ = __shfl_up_sync(0xffffffffu, v__[7], 1);                      \
    float vR__ = __shfl_down_sync(0xffffffffu, v__[0], 1);                    \
    if (lane == 0)  { uL__ = u__[1]; vL__ = v__[1]; }                         \
    if (lane == 31) { uR__ = u__[6]; vR__ = v__[6]; }                         \
    _Pragma("unroll")                                                         \
    for (int i=0;i<8;i++){                                                    \
        float um1__ = (i==0)? uL__ : u__[i-1];                                \
        float up1__ = (i==7)? uR__ : u__[i+1];                                \
        float vm1__ = (i==0)? vL__ : v__[i-1];                                \
        float vp1__ = (i==7)? vR__ : v__[i+1];                                \
        float dx__ = (up1__ - um1__) * SC;                                    \
        float dy__ = (fmaf(2.0f, v__[i], vm1__) + vp1__) * SC;                \
        AX[i] = dx__*dx__; AXY[i] = dx__*dy__; AY[i] = dy__*dy__;             \
    }                                                                         \
    _Pragma("unroll")                                                         \
    for (int i=0;i<8;i++){ xa[i] = xb[i]; xb[i] = xc__[i]; }                  \
} while(0)

// Horizontal sums + R + horiz 3-max + emit dst row q = PV-1 (uses sxx/sxy/syy).
// mb is initialized to -inf so dv = max(mb,ma,mc) is uniform (top clip free).
#define EMIT_P(PV) do {                                                       \
    float xxL__ = __shfl_up_sync(0xffffffffu, sxx[7],1);                      \
    float xxR__ = __shfl_down_sync(0xffffffffu, sxx[0],1);                    \
    float xyL__ = __shfl_up_sync(0xffffffffu, sxy[7],1);                      \
    float xyR__ = __shfl_down_sync(0xffffffffu, sxy[0],1);                    \
    float yyL__ = __shfl_up_sync(0xffffffffu, syy[7],1);                      \
    float yyR__ = __shfl_down_sync(0xffffffffu, syy[0],1);                    \
    if (lane==0){  xxL__=sxx[1]; xyL__=sxy[1]; yyL__=syy[1]; }                \
    if (lane==31){ xxR__=sxx[6]; xyR__=sxy[6]; yyR__=syy[6]; }                \
    float Rv__[8];                                                            \
    _Pragma("unroll")                                                         \
    for (int i=0;i<8;i++){                                                    \
        float ixx = (((i==0)?xxL__:sxx[i-1]) + sxx[i]) + ((i==7)?xxR__:sxx[i+1]);\
        float ixy = (((i==0)?xyL__:sxy[i-1]) + sxy[i]) + ((i==7)?xyR__:sxy[i+1]);\
        float iyy = (((i==0)?yyL__:syy[i-1]) + syy[i]) + ((i==7)?yyR__:syy[i+1]);\
        float t1__ = ixy * ixy;                                               \
        float det__ = fmaf(ixx, iyy, -t1__);                                  \
        float tr__  = ixx + iyy;                                              \
        float t2__ = tr__ * tr__;                                             \
        Rv__[i] = fmaf(-0.04f, t2__, det__);                                  \
    }                                                                         \
    float RL__ = __shfl_up_sync(0xffffffffu, Rv__[7],1);                      \
    float RR__ = __shfl_down_sync(0xffffffffu, Rv__[0],1);                    \
    if (lane==0)  RL__ = -CUDART_INF_F;                                       \
    if (lane==31) RR__ = -CUDART_INF_F;                                       \
    float mc__[8];                                                            \
    _Pragma("unroll")                                                         \
    for (int i=0;i<8;i++){                                                    \
        float l__ = (i==0)?RL__:Rv__[i-1];                                    \
        float r__ = (i==7)?RR__:Rv__[i+1];                                    \
        mc__[i] = fmaxf(fmaxf(l__, Rv__[i]), r__);                            \
    }                                                                         \
    int q__ = (PV) - 1;                                                       \
    if (q__ >= r0) {                                                          \
        float lm__ = fmaxf(fmaxf(mb[0],ma[0]),mc__[0]);                       \
        _Pragma("unroll")                                                     \
        for (int i=1;i<8;i++)                                                 \
            lm__ = fmaxf(lm__, fmaxf(fmaxf(mb[i],ma[i]),mc__[i]));            \
        lmax = fmaxf(lmax, lm__);                                             \
        g_cmax32[((img<<8)+q__)*32 + lane] = lm__;                            \
    }                                                                         \
    _Pragma("unroll")                                                         \
    for (int i=0;i<8;i++){ mb[i]=ma[i]; ma[i]=mc__[i]; }                      \
} while(0)

__global__ void __launch_bounds__(32, 16) harris_kernel(const float* __restrict__ x,
                                                        float* __restrict__ out) {
    if (blockIdx.x == 0 && threadIdx.x == 0) g_count = 0;   // reset list
    const int img  = blockIdx.x >> 4;
    const int seg  = blockIdx.x & (NSEG - 1);
    const int lane = threadIdx.x;
    const int cb   = lane * 8;
    const float* __restrict__ xim = x + (size_t)img * HWSZ;
    float* __restrict__ oim = out + (size_t)img * HWSZ;

    const int r0 = seg * SEGROWS;
    const int r1 = r0 + SEGROWS;

    // out = x for this segment's rows (patched later only at rare corners)
    for (int r = r0; r < r1; ++r) {
        const float4* ps = reinterpret_cast<const float4*>(xim + r * WW + cb);
        float4 a0 = ps[0], a1 = ps[1];
        float4* po = reinterpret_cast<float4*>(oim + r * WW + cb);
        po[0] = a0; po[1] = a1;
    }

    const float SC = (1.0f / 12.0f);   // SOBEL_SCALE
    float xa[8], xb[8];
    float p2x[8], p2y[8], p2z[8];      // P2 = dd(p-1)+dd(p)   (xx,xy,yy)
    float cx[8],  cy[8],  cz[8];       // C  = dd(p)
    float ma[8], mb[8];                // horizontal-max windows m(p-1), m(p-2)
    float lmax = -CUDART_INF_F;

#pragma unroll
    for (int i=0;i<8;i++){ ma[i] = -CUDART_INF_F; mb[i] = -CUDART_INF_F; }

    int pstart;
    if (r0 == 0) {
        LOAD_XROW(-1, xa);
        LOAD_XROW(0,  xb);
        COMPUTE_DD(0, cx, cy, cz);
#pragma unroll
        for (int i=0;i<8;i++){ p2x[i]=cx[i]+cx[i]; p2y[i]=cy[i]+cy[i]; p2z[i]=cz[i]+cz[i]; }
        // peeled p == 0 iteration (emits q=-1: nothing; shifts ma/mb)
        {
            float nx[8], ny[8], nz[8];
            COMPUTE_DD(1, nx, ny, nz);
            float sxx[8], sxy[8], syy[8];
#pragma unroll
            for (int i=0;i<8;i++){ sxx[i]=fmaf(2.0f, nx[i], cx[i]);
                                   sxy[i]=fmaf(2.0f, ny[i], cy[i]);
                                   syy[i]=fmaf(2.0f, nz[i], cz[i]); }
#pragma unroll
            for (int i=0;i<8;i++){ p2x[i]=cx[i]+nx[i]; cx[i]=nx[i];
                                   p2y[i]=cy[i]+ny[i]; cy[i]=ny[i];
                                   p2z[i]=cz[i]+nz[i]; cz[i]=nz[i]; }
            EMIT_P(0);
        }
        pstart = 1;
    } else {
        float d1x[8], d1y[8], d1z[8];
        LOAD_XROW(r0 - 3, xa);
        LOAD_XROW(r0 - 2, xb);
        COMPUTE_DD(r0 - 2, d1x, d1y, d1z);
        COMPUTE_DD(r0 - 1, cx, cy, cz);
#pragma unroll
        for (int i=0;i<8;i++){ p2x[i]=d1x[i]+cx[i]; p2y[i]=d1y[i]+cy[i]; p2z[i]=d1z[i]+cz[i]; }
        pstart = r0 - 1;
    }

    const int pend = (r1 == HH) ? (HH - 1) : (r1 + 1);
#pragma unroll 2
    for (int p = pstart; p < pend; ++p) {
        float nx[8], ny[8], nz[8];
        COMPUTE_DD(p+1, nx, ny, nz);
        float sxx[8], sxy[8], syy[8];
#pragma unroll
        for (int i=0;i<8;i++){ sxx[i]=p2x[i]+nx[i];
                               sxy[i]=p2y[i]+ny[i];
                               syy[i]=p2z[i]+nz[i]; }
#pragma unroll
        for (int i=0;i<8;i++){ p2x[i]=cx[i]+nx[i]; cx[i]=nx[i];
                               p2y[i]=cy[i]+ny[i]; cy[i]=ny[i];
                               p2z[i]=cz[i]+nz[i]; cz[i]=nz[i]; }
        EMIT_P(p);
    }

    if (r1 == HH) {
        // peel p = 255: vertical sum = dd(255) + 2*(p2-dd(255)) (= +2*dd(254))
        float sxx[8], sxy[8], syy[8];
#pragma unroll
        for (int i=0;i<8;i++){
            sxx[i] = fmaf(2.0f, p2x[i] - cx[i], cx[i]);
            sxy[i] = fmaf(2.0f, p2y[i] - cy[i], cy[i]);
            syy[i] = fmaf(2.0f, p2z[i] - cz[i], cz[i]);
        }
        EMIT_P(255);
        // bottom image row: dst(255) = max(m(254), m(255))
        float lm = fmaxf(mb[0], ma[0]);
#pragma unroll
        for (int i=1;i<8;i++) lm = fmaxf(lm, fmaxf(mb[i], ma[i]));
        lmax = fmaxf(lmax, lm);
        g_cmax32[((img<<8)+(HH-1))*32 + lane] = lm;
    }

#pragma unroll
    for (int o=16;o;o>>=1) lmax = fmaxf(lmax, __shfl_xor_sync(0xffffffffu, lmax, o));
    if (lane == 0) g_segmax[img * NSEG + seg] = lmax;
}

// ---------------------------------------------------------------------------
// Scan: compute t per image, compact flagged chunks (cmax >= t) into g_list
// with warp-aggregated atomics. Each thread covers 2 chunks via one float4.
// Grid: 4096 blocks x 256 (8 blocks per image).
// ---------------------------------------------------------------------------
__global__ void scan_kernel() {
    __shared__ float s16[16];
    const int img = blockIdx.x >> 3;
    if (threadIdx.x < 16) s16[threadIdx.x] = g_segmax[img * NSEG + threadIdx.x];
    __syncthreads();
    float m = s16[0];
#pragma unroll
    for (int i=1;i<16;i++) m = fmaxf(m, s16[i]);
    const float t = 0.7f * m;   // THRESH_FRAC
    if ((blockIdx.x & 7) == 0 && threadIdx.x == 0) g_tmax[img] = t;

    int pair = blockIdx.x * 256 + threadIdx.x;      // 2 chunks per thread
    float4 v = *reinterpret_cast<const float4*>(g_cmax32 + (size_t)pair * 4);
    int cid0 = pair * 2;
    bool f0 = fmaxf(v.x, v.y) >= t;
    bool f1 = fmaxf(v.z, v.w) >= t;

    unsigned b0 = __ballot_sync(0xffffffffu, f0);
    unsigned b1 = __ballot_sync(0xffffffffu, f1);
    int n0 = __popc(b0);
    int tot = n0 + __popc(b1);
    if (tot) {
        int lane = threadIdx.x & 31;
        unsigned lt = (1u << lane) - 1u;
        int basep = 0;
        if (lane == 0) basep = atomicAdd(&g_count, tot);
        basep = __shfl_sync(0xffffffffu, basep, 0);
        if (f0) g_list[basep + __popc(b0 & lt)] = cid0;
        if (f1) g_list[basep + n0 + __popc(b1 & lt)] = cid0 + 1;
    }
}

// ---------------------------------------------------------------------------
// Apply: grid-stride warps over the compacted list (load-balanced). One warp
// per flagged chunk: 21 upfront parallel x loads, recompute dst bit-identical
// to pass A, lane-parallel conv1x1 for flagged pixels; overwrite out.
// ---------------------------------------------------------------------------
__global__ void apply_kernel(const float* __restrict__ x, const float* __restrict__ wt,
                             const float* __restrict__ bias, float* __restrict__ out) {
    const int gwarp  = (blockIdx.x * blockDim.x + threadIdx.x) >> 5;
    const int nwarps = (gridDim.x * blockDim.x) >> 5;
    const int lane = threadIdx.x & 31;
    const float SC = (1.0f / 12.0f);
    const int total = g_count;

    for (int li = gwarp; li < total; li += nwarps) {
        int cid = g_list[li];
        int img = cid >> 12;
        int rc  = cid & 4095;
        int q   = rc >> 4;
        int c0  = (rc & 15) << 4;
        float t = g_tmax[img];
        const float* __restrict__ xim = x + (size_t)img * HWSZ;

        int c  = c0 - 2 + lane;                 // field column
        int cc = (c < 0) ? -c : (c >= WW ? 2*WW - 2 - c : c);
        int cL = (cc == 0) ? 1 : cc - 1;        // reflect-101 col for x loads
        int cR = (cc == WW-1) ? WW-2 : cc + 1;

        int dlo = q - 2 < 0 ? 0 : q - 2;
        int dhi = q + 2 > HH-1 ? HH-1 : q + 2;

        // Upfront parallel loads: 7 rows x 3 cols (rows beyond the needed
        // span load valid reflected rows; their dd results are discarded).
        float xr0[7], xr1[7], xr2[7];
#pragma unroll
        for (int j = 0; j < 7; ++j) {
            int rj = rrow(dlo - 1 + j) * WW;
            xr0[j] = xim[rj + cL];
            xr1[j] = xim[rj + cc];
            xr2[j] = xim[rj + cR];
        }
        float xq = xim[q * WW + cc];            // x at (q, cc) for the mask

        float ddx[5], ddxy[5], ddy2[5];
#pragma unroll
        for (int k = 0; k < 5; ++k) {           // d = dlo + k (k>span unused)
            float uL = fmaf(2.0f, xr0[k+1], xr0[k]) + xr0[k+2];
            float uR = fmaf(2.0f, xr2[k+1], xr2[k]) + xr2[k+2];
            float vL = xr0[k+2] - xr0[k];
            float vC = xr1[k+2] - xr1[k];
            float vR = xr2[k+2] - xr2[k];
            float dx = (uR - uL) * SC;
            float dy = (fmaf(2.0f, vC, vL) + vR) * SC;
            ddx[k]  = dx * dx;
            ddxy[k] = dx * dy;
            ddy2[k] = dy * dy;
        }

        float dstv = -CUDART_INF_F;
        for (int rr = q - 1; rr <= q + 1; ++rr) {
            if (rr < 0 || rr > HH - 1) continue;
            float sxx, sxy, syy;
            if (rr == 0) {
                sxx = fmaf(2.0f, ddx[CL(1 - dlo)],  ddx[CL(0 - dlo)]);
                sxy = fmaf(2.0f, ddxy[CL(1 - dlo)], ddxy[CL(0 - dlo)]);
                syy = fmaf(2.0f, ddy2[CL(1 - dlo)], ddy2[CL(0 - dlo)]);
            } else if (rr == HH - 1) {
                float p2a = ddx[CL(254 - dlo)]  + ddx[CL(255 - dlo)];
                float p2b = ddxy[CL(254 - dlo)] + ddxy[CL(255 - dlo)];
                float p2c = ddy2[CL(254 - dlo)] + ddy2[CL(255 - dlo)];
                sxx = fmaf(2.0f, p2a - ddx[CL(255 - dlo)],  ddx[CL(255 - dlo)]);
                sxy = fmaf(2.0f, p2b - ddxy[CL(255 - dlo)], ddxy[CL(255 - dlo)]);
                syy = fmaf(2.0f, p2c - ddy2[CL(255 - dlo)], ddy2[CL(255 - dlo)]);
            } else {
                sxx = (ddx[CL(rr - 1 - dlo)]  + ddx[CL(rr - dlo)])  + ddx[CL(rr + 1 - dlo)];
                sxy = (ddxy[CL(rr - 1 - dlo)] + ddxy[CL(rr - dlo)]) + ddxy[CL(rr + 1 - dlo)];
                syy = (ddy2[CL(rr - 1 - dlo)] + ddy2[CL(rr - dlo)]) + ddy2[CL(rr + 1 - dlo)];
            }
            float xxm = __shfl_up_sync(0xffffffffu, sxx, 1);
            float xxp = __shfl_down_sync(0xffffffffu, sxx, 1);
            float xym = __shfl_up_sync(0xffffffffu, sxy, 1);
            float xyp = __shfl_down_sync(0xffffffffu, sxy, 1);
            float yym = __shfl_up_sync(0xffffffffu, syy, 1);
            float yyp = __shfl_down_sync(0xffffffffu, syy, 1);
            float ixx = (xxm + sxx) + xxp;
            float ixy = (xym + sxy) + xyp;
            float iyy = (yym + syy) + yyp;
            float t1 = ixy * ixy;
            float det = fmaf(ixx, iyy, -t1);
            float tr  = ixx + iyy;
            float t2 = tr * tr;
            float Rv = fmaf(-0.04f, t2, det);
            if (c < 0 || c > WW - 1) Rv = -CUDART_INF_F;   // dilation clips
            float Rm = __shfl_up_sync(0xffffffffu, Rv, 1);
            float Rp = __shfl_down_sync(0xffffffffu, Rv, 1);
            float mm = fmaxf(fmaxf(Rm, Rv), Rp);
            dstv = fmaxf(dstv, mm);
        }

        bool flg = (lane >= 2) && (lane < 18) && (dstv >= t);
        unsigned bal = __ballot_sync(0xffffffffu, flg);
        if (bal) {
            int b   = img >> 6;
            int cch = img & 63;
            float w0 = wt[(cch << 6) + 2*lane];
            float w1 = wt[(cch << 6) + 2*lane + 1];
            float bi = bias[cch];
            const float* xbase = x + (size_t)(b << 6) * HWSZ;
            while (bal) {
                int lp = __ffs(bal) - 1; bal &= bal - 1;
                int pix = (q << 8) + c0 + lp - 2;
                float xv0 = xbase[(size_t)(2*lane)     * HWSZ + pix];
                float xv1 = xbase[(size_t)(2*lane + 1) * HWSZ + pix];
                float acc = fmaf(w0, xv0, w1 * xv1);
#pragma unroll
                for (int o = 16; o; o >>= 1)
                    acc += __shfl_xor_sync(0xffffffffu, acc, o);
                if (lane == lp) {
                    float y = fmaxf(acc + bi, 0.0f);
                    float mask = (dstv > t) ? 1.0f : xq;   // tie keeps pixel
                    out[(size_t)img * HWSZ + pix] = fmaf(mask, y, xq);
                }
            }
        }
    }
}

extern "C" void kernel_launch(void* const* d_in, const int* in_sizes, int n_in,
                              void* d_out, int out_size) {
    const float* x = (const float*)d_in[0];
    const float* w = (const float*)d_in[1];
    const float* b = (const float*)d_in[2];
    float* out = (float*)d_out;
    harris_kernel<<<NIMG * NSEG, 32>>>(x, out);
    scan_kernel<<<4096, 256>>>();
    apply_kernel<<<512, 256>>>(x, w, b, out);
}